// round 2
// baseline (speedup 1.0000x reference)
#include <cuda_runtime.h>
#include <math.h>

// ---------------- problem constants ----------------
#define B_    2
#define L_    1024
#define D_    1024
#define H_    16
#define DH_   64
#define E_    32
#define ES_   128
#define K_    4
#define T_    (B_*L_)        // 2048 tokens
#define P2_   (2*L_-1)       // 2047 relative positions
#define NC_   (E_*ES_)       // 4096 MoE hidden concat

// ---------------- scratch (static __device__, no allocation) ----------------
__device__ float g_pe [P2_ * D_];          // sinusoidal pos enc      8.4 MB
__device__ float g_x2 [T_ * D_];           // ln1 output              8.4 MB
__device__ float g_qb [T_ * D_];
__device__ float g_kb [T_ * D_];
__device__ float g_vb [T_ * D_];
__device__ float g_pb [P2_ * D_];          // pos proj
__device__ float g_sc [(size_t)B_*H_*L_*L_];  // attention scores     134 MB
__device__ float g_ctx[T_ * D_];
__device__ float g_xr [T_ * D_];           // residual after attn
__device__ float g_tb [T_ * D_];           // ln2 output
__device__ float g_gate[T_ * E_];
__device__ float g_hb [T_ * NC_];          // MoE hidden             33.6 MB

// ---------------- sinusoidal positional encoding ----------------
__global__ __launch_bounds__(256) void k_pos(float* __restrict__ pe) {
    int r = blockIdx.x;                    // 0..2046
    double pos = (double)(L_ - 1 - r);
    const double c = -9.210340371976184 / (double)D_;   // -ln(10000)/D
    for (int m = threadIdx.x; m < D_; m += 256) {
        int j = (m < D_/2) ? m : m - D_/2;
        double ang = pos * exp(c * (2.0 * (double)j));
        pe[(size_t)r * D_ + m] = (float)((m < D_/2) ? sin(ang) : cos(ang));
    }
}

// ---------------- layer norm (one block per row of 1024) ----------------
__global__ __launch_bounds__(256) void k_ln(const float* __restrict__ x,
                                            const float* __restrict__ g,
                                            const float* __restrict__ b,
                                            float* __restrict__ o) {
    __shared__ float rs[256], rq[256];
    size_t row = blockIdx.x;
    int tid = threadIdx.x;
    float4 v = reinterpret_cast<const float4*>(x + row * D_)[tid];
    rs[tid] = v.x + v.y + v.z + v.w;
    rq[tid] = v.x*v.x + v.y*v.y + v.z*v.z + v.w*v.w;
    __syncthreads();
    for (int s = 128; s; s >>= 1) {
        if (tid < s) { rs[tid] += rs[tid+s]; rq[tid] += rq[tid+s]; }
        __syncthreads();
    }
    float mean = rs[0] * (1.0f / D_);
    float var  = rq[0] * (1.0f / D_) - mean * mean;
    float inv  = rsqrtf(var + 1e-5f);
    float4 gv = reinterpret_cast<const float4*>(g)[tid];
    float4 bv = reinterpret_cast<const float4*>(b)[tid];
    float4 out;
    out.x = (v.x - mean) * inv * gv.x + bv.x;
    out.y = (v.y - mean) * inv * gv.y + bv.y;
    out.z = (v.z - mean) * inv * gv.z + bv.z;
    out.w = (v.w - mean) * inv * gv.w + bv.w;
    reinterpret_cast<float4*>(o + row * D_)[tid] = out;
}

// ---------------- generic SGEMM: C[M,N] = A[M,K]@B[K,N] (+aux residual) ----------------
// 64x64 block tile, BK=16, 256 threads, 4x4 register tile per thread.
// EPI: 0 = none, 1 = += aux[m*N+n]
template<int EPI>
__global__ __launch_bounds__(256) void k_sgemm(const float* __restrict__ A,
                                               const float* __restrict__ Bm,
                                               float* __restrict__ C,
                                               const float* __restrict__ aux,
                                               int M, int N, int K) {
    __shared__ float As[16][65];
    __shared__ float Bs[16][64];
    const int tid = threadIdx.x;
    const int tx = tid & 15, ty = tid >> 4;
    const int m0 = blockIdx.y * 64, n0 = blockIdx.x * 64;
    const int lkA = tid & 15, lmA = tid >> 4;     // A loader
    const int lnB = tid & 63, lkB = tid >> 6;     // B loader
    float acc[4][4] = {};
    for (int k0 = 0; k0 < K; k0 += 16) {
#pragma unroll
        for (int r = 0; r < 4; r++) {
            int m = m0 + lmA + r * 16;
            As[lkA][lmA + r * 16] = (m < M) ? A[(size_t)m * K + k0 + lkA] : 0.f;
        }
#pragma unroll
        for (int r = 0; r < 4; r++) {
            int kk = lkB + r * 4;
            Bs[kk][lnB] = Bm[(size_t)(k0 + kk) * N + n0 + lnB];
        }
        __syncthreads();
#pragma unroll
        for (int kk = 0; kk < 16; kk++) {
            float a0 = As[kk][ty*4+0], a1 = As[kk][ty*4+1];
            float a2 = As[kk][ty*4+2], a3 = As[kk][ty*4+3];
            float4 bq = *reinterpret_cast<const float4*>(&Bs[kk][tx*4]);
            acc[0][0] += a0*bq.x; acc[0][1] += a0*bq.y; acc[0][2] += a0*bq.z; acc[0][3] += a0*bq.w;
            acc[1][0] += a1*bq.x; acc[1][1] += a1*bq.y; acc[1][2] += a1*bq.z; acc[1][3] += a1*bq.w;
            acc[2][0] += a2*bq.x; acc[2][1] += a2*bq.y; acc[2][2] += a2*bq.z; acc[2][3] += a2*bq.w;
            acc[3][0] += a3*bq.x; acc[3][1] += a3*bq.y; acc[3][2] += a3*bq.z; acc[3][3] += a3*bq.w;
        }
        __syncthreads();
    }
#pragma unroll
    for (int i = 0; i < 4; i++) {
        int m = m0 + ty * 4 + i;
        if (m < M) {
#pragma unroll
            for (int j = 0; j < 4; j++) {
                int n = n0 + tx * 4 + j;
                float v = acc[i][j];
                if (EPI == 1) v += aux[(size_t)m * N + n];
                C[(size_t)m * N + n] = v;
            }
        }
    }
}

// ---------------- MoE up-proj: H[t, e*128+j] = relu(t . keys[e,:,j]) * gate[t,e] ----------------
__global__ __launch_bounds__(256) void k_moeup(const float* __restrict__ A,
                                               const float* __restrict__ keys,
                                               const float* __restrict__ gate,
                                               float* __restrict__ C) {
    __shared__ float As[16][65];
    __shared__ float Bs[16][64];
    const int tid = threadIdx.x;
    const int tx = tid & 15, ty = tid >> 4;
    const int m0 = blockIdx.y * 64, n0 = blockIdx.x * 64;
    const int e  = n0 >> 7;                 // 64-wide tile lies within one expert chunk
    const int jb = n0 & 127;
    const int lkA = tid & 15, lmA = tid >> 4;
    const int lnB = tid & 63, lkB = tid >> 6;
    const float* kbase = keys + (size_t)e * D_ * ES_ + jb;
    float acc[4][4] = {};
    for (int k0 = 0; k0 < D_; k0 += 16) {
#pragma unroll
        for (int r = 0; r < 4; r++) {
            int m = m0 + lmA + r * 16;
            As[lkA][lmA + r * 16] = A[(size_t)m * D_ + k0 + lkA];
        }
#pragma unroll
        for (int r = 0; r < 4; r++) {
            int kk = lkB + r * 4;
            Bs[kk][lnB] = kbase[(size_t)(k0 + kk) * ES_ + lnB];
        }
        __syncthreads();
#pragma unroll
        for (int kk = 0; kk < 16; kk++) {
            float a0 = As[kk][ty*4+0], a1 = As[kk][ty*4+1];
            float a2 = As[kk][ty*4+2], a3 = As[kk][ty*4+3];
            float4 bq = *reinterpret_cast<const float4*>(&Bs[kk][tx*4]);
            acc[0][0] += a0*bq.x; acc[0][1] += a0*bq.y; acc[0][2] += a0*bq.z; acc[0][3] += a0*bq.w;
            acc[1][0] += a1*bq.x; acc[1][1] += a1*bq.y; acc[1][2] += a1*bq.z; acc[1][3] += a1*bq.w;
            acc[2][0] += a2*bq.x; acc[2][1] += a2*bq.y; acc[2][2] += a2*bq.z; acc[2][3] += a2*bq.w;
            acc[3][0] += a3*bq.x; acc[3][1] += a3*bq.y; acc[3][2] += a3*bq.z; acc[3][3] += a3*bq.w;
        }
        __syncthreads();
    }
#pragma unroll
    for (int i = 0; i < 4; i++) {
        int m = m0 + ty * 4 + i;
        float gv = gate[m * E_ + e];
#pragma unroll
        for (int j = 0; j < 4; j++) {
            int n = n0 + tx * 4 + j;
            C[(size_t)m * NC_ + n] = fmaxf(acc[i][j], 0.f) * gv;
        }
    }
}

// ---------------- attention scores with fused rel-pos band gather ----------------
// scores[bh,i,j] = ( q_i . (k_j + p[j-i+L-1]) ) / 8
__global__ __launch_bounds__(256) void k_scores(const float* __restrict__ q,
                                                const float* __restrict__ k,
                                                const float* __restrict__ p,
                                                float* __restrict__ sc) {
    __shared__ float Qs[32][65], Ks[32][65], Ps[63][65];
    const int bh = blockIdx.z;
    const int b = bh / H_, h = bh % H_;
    const int i0 = blockIdx.y * 32, j0 = blockIdx.x * 32;
    const int tid = threadIdx.x;
    {
        int d = tid & 63, rb = tid >> 6;      // 4 rows / pass
#pragma unroll
        for (int r = 0; r < 32; r += 4)
            Qs[rb + r][d] = q[(size_t)(b*L_ + i0 + rb + r) * D_ + h*DH_ + d];
#pragma unroll
        for (int r = 0; r < 32; r += 4)
            Ks[rb + r][d] = k[(size_t)(b*L_ + j0 + rb + r) * D_ + h*DH_ + d];
        int base = j0 - i0 + L_ - 32;         // global idx of band row 0, always in [0, 2L-2-62]
#pragma unroll
        for (int r = 0; r < 64; r += 4) {
            int rr = rb + r;
            if (rr < 63)
                Ps[rr][d] = p[(size_t)(base + rr) * D_ + h*DH_ + d];
        }
    }
    __syncthreads();
    const int tx = tid & 31, ty = tid >> 5;    // j = tx, i = ty*4+ii
    float s[4] = {0.f, 0.f, 0.f, 0.f};
    for (int d = 0; d < 64; d++) {
        float kv = Ks[tx][d];
#pragma unroll
        for (int ii = 0; ii < 4; ii++) {
            int il = ty * 4 + ii;
            s[ii] += Qs[il][d] * (kv + Ps[tx - il + 31][d]);
        }
    }
#pragma unroll
    for (int ii = 0; ii < 4; ii++) {
        int i = i0 + ty * 4 + ii;
        sc[((size_t)bh * L_ + i) * L_ + j0 + tx] = s[ii] * 0.125f;
    }
}

// ---------------- row softmax over scores (in place) ----------------
__global__ __launch_bounds__(256) void k_softmax(float* __restrict__ sc) {
    __shared__ float red[256];
    size_t row = blockIdx.x;
    float* r = sc + row * L_;
    int tid = threadIdx.x;
    float4 v = reinterpret_cast<float4*>(r)[tid];
    red[tid] = fmaxf(fmaxf(v.x, v.y), fmaxf(v.z, v.w));
    __syncthreads();
    for (int s = 128; s; s >>= 1) {
        if (tid < s) red[tid] = fmaxf(red[tid], red[tid+s]);
        __syncthreads();
    }
    float mx = red[0];
    __syncthreads();
    v.x = expf(v.x - mx); v.y = expf(v.y - mx);
    v.z = expf(v.z - mx); v.w = expf(v.w - mx);
    red[tid] = v.x + v.y + v.z + v.w;
    __syncthreads();
    for (int s = 128; s; s >>= 1) {
        if (tid < s) red[tid] += red[tid+s];
        __syncthreads();
    }
    float inv = 1.f / red[0];
    v.x *= inv; v.y *= inv; v.z *= inv; v.w *= inv;
    reinterpret_cast<float4*>(r)[tid] = v;
}

// ---------------- ctx = att @ v, written in [b, i, h*64+d] layout ----------------
__global__ __launch_bounds__(256) void k_av(const float* __restrict__ sc,
                                            const float* __restrict__ v,
                                            float* __restrict__ ctx) {
    __shared__ float As[64][33];
    __shared__ float Vs[32][64];
    const int bh = blockIdx.y, b = bh / H_, h = bh % H_;
    const int i0 = blockIdx.x * 64;
    const int tid = threadIdx.x;
    const int tx = tid & 15, ty = tid >> 4;
    float acc[4][4] = {};
    for (int j0 = 0; j0 < L_; j0 += 32) {
        {
            int kk = tid & 31, ib = tid >> 5;
#pragma unroll
            for (int r = 0; r < 64; r += 8)
                As[ib + r][kk] = sc[((size_t)bh * L_ + i0 + ib + r) * L_ + j0 + kk];
            int d = tid & 63, kb2 = tid >> 6;
#pragma unroll
            for (int r = 0; r < 32; r += 4)
                Vs[kb2 + r][d] = v[(size_t)(b*L_ + j0 + kb2 + r) * D_ + h*DH_ + d];
        }
        __syncthreads();
#pragma unroll
        for (int kk = 0; kk < 32; kk++) {
            float a0 = As[ty*4+0][kk], a1 = As[ty*4+1][kk];
            float a2 = As[ty*4+2][kk], a3 = As[ty*4+3][kk];
            float4 bq = *reinterpret_cast<const float4*>(&Vs[kk][tx*4]);
            acc[0][0] += a0*bq.x; acc[0][1] += a0*bq.y; acc[0][2] += a0*bq.z; acc[0][3] += a0*bq.w;
            acc[1][0] += a1*bq.x; acc[1][1] += a1*bq.y; acc[1][2] += a1*bq.z; acc[1][3] += a1*bq.w;
            acc[2][0] += a2*bq.x; acc[2][1] += a2*bq.y; acc[2][2] += a2*bq.z; acc[2][3] += a2*bq.w;
            acc[3][0] += a3*bq.x; acc[3][1] += a3*bq.y; acc[3][2] += a3*bq.z; acc[3][3] += a3*bq.w;
        }
        __syncthreads();
    }
#pragma unroll
    for (int i = 0; i < 4; i++)
#pragma unroll
        for (int j = 0; j < 4; j++)
            ctx[(size_t)(b*L_ + i0 + ty*4 + i) * D_ + h*DH_ + tx*4 + j] = acc[i][j];
}

// ---------------- gating: sigmoid(t @ sel_w), top-4, masked gate row ----------------
__global__ __launch_bounds__(256) void k_gates(const float* __restrict__ t,
                                               const float* __restrict__ sw,
                                               float* __restrict__ gate) {
    __shared__ float ts[D_];
    const int tok = blockIdx.x;
    const int tid = threadIdx.x;
    reinterpret_cast<float4*>(ts)[tid] =
        reinterpret_cast<const float4*>(t + (size_t)tok * D_)[tid];
    __syncthreads();
    if (tid < 32) {
        float acc = 0.f;
        for (int d = 0; d < D_; d++) acc += ts[d] * sw[d * E_ + tid];
        float gv = 1.f / (1.f + expf(-acc));
        bool sel = false;
        for (int r = 0; r < K_; r++) {
            float cand = sel ? -1e30f : gv;
            float bv = cand; int bi = tid;
            for (int off = 16; off; off >>= 1) {
                float ov = __shfl_xor_sync(0xffffffffu, bv, off);
                int oi = __shfl_xor_sync(0xffffffffu, bi, off);
                if (ov > bv || (ov == bv && oi < bi)) { bv = ov; bi = oi; }
            }
            if (tid == bi) sel = true;
        }
        gate[tok * E_ + tid] = sel ? gv : 0.f;
    }
}

// ---------------- launch ----------------
extern "C" void kernel_launch(void* const* d_in, const int* in_sizes, int n_in,
                              void* d_out, int out_size) {
    const float* src  = (const float*)d_in[0];
    const float* Wq   = (const float*)d_in[1];
    const float* Wk   = (const float*)d_in[2];
    const float* Wv   = (const float*)d_in[3];
    const float* Wo   = (const float*)d_in[4];
    const float* Wp   = (const float*)d_in[5];
    const float* ln1g = (const float*)d_in[6];
    const float* ln1b = (const float*)d_in[7];
    const float* ln2g = (const float*)d_in[8];
    const float* ln2b = (const float*)d_in[9];
    const float* selw = (const float*)d_in[10];
    const float* keys = (const float*)d_in[11];
    const float* vals = (const float*)d_in[12];
    float* out = (float*)d_out;

    float *pe, *x2, *qb, *kb, *vb, *pb, *sc, *ctx, *xr, *tb, *gate, *hb;
    cudaGetSymbolAddress((void**)&pe,  g_pe);
    cudaGetSymbolAddress((void**)&x2,  g_x2);
    cudaGetSymbolAddress((void**)&qb,  g_qb);
    cudaGetSymbolAddress((void**)&kb,  g_kb);
    cudaGetSymbolAddress((void**)&vb,  g_vb);
    cudaGetSymbolAddress((void**)&pb,  g_pb);
    cudaGetSymbolAddress((void**)&sc,  g_sc);
    cudaGetSymbolAddress((void**)&ctx, g_ctx);
    cudaGetSymbolAddress((void**)&xr,  g_xr);
    cudaGetSymbolAddress((void**)&tb,  g_tb);
    cudaGetSymbolAddress((void**)&gate,g_gate);
    cudaGetSymbolAddress((void**)&hb,  g_hb);

    // positional encoding + ln1
    k_pos<<<P2_, 256>>>(pe);
    k_ln<<<T_, 256>>>(src, ln1g, ln1b, x2);

    // projections
    dim3 gProj(D_/64, T_/64);               // (16, 32)
    k_sgemm<0><<<gProj, 256>>>(x2, Wq, qb, nullptr, T_, D_, D_);
    k_sgemm<0><<<gProj, 256>>>(x2, Wk, kb, nullptr, T_, D_, D_);
    k_sgemm<0><<<gProj, 256>>>(x2, Wv, vb, nullptr, T_, D_, D_);
    k_sgemm<0><<<dim3(D_/64, (P2_+63)/64), 256>>>(pe, Wp, pb, nullptr, P2_, D_, D_);

    // attention
    k_scores<<<dim3(L_/32, L_/32, B_*H_), 256>>>(qb, kb, pb, sc);
    k_softmax<<<B_*H_*L_, 256>>>(sc);
    k_av<<<dim3(L_/64, B_*H_), 256>>>(sc, vb, ctx);
    k_sgemm<1><<<gProj, 256>>>(ctx, Wo, xr, src, T_, D_, D_);   // + residual(src)

    // MoE block
    k_ln<<<T_, 256>>>(xr, ln2g, ln2b, tb);
    k_gates<<<T_, 256>>>(tb, selw, gate);
    k_moeup<<<dim3(NC_/64, T_/64), 256>>>(tb, keys, gate, hb);
    k_sgemm<1><<<gProj, 256>>>(hb, vals, out, xr, T_, D_, NC_); // + residual(xr)
}

// round 5
// speedup vs baseline: 1.5838x; 1.5838x over previous
#include <cuda_runtime.h>
#include <cuda_fp16.h>
#include <math.h>
#include <stdint.h>

#define B_    2
#define L_    1024
#define D_    1024
#define H_    16
#define DH_   64
#define E_    32
#define ES_   128
#define T_    (B_*L_)
#define P2_   (2*L_-1)
#define NC_   (E_*ES_)

typedef __half half_t;

// ---------------- warp MMA helpers ----------------
__device__ __forceinline__ uint32_t smem_u32(const void* p) {
    uint32_t a;
    asm("{ .reg .u64 t; cvta.to.shared.u64 t, %1; cvt.u32.u64 %0, t; }" : "=r"(a) : "l"(p));
    return a;
}
__device__ __forceinline__ void ldsm4(uint32_t& r0, uint32_t& r1, uint32_t& r2, uint32_t& r3, uint32_t addr) {
    asm volatile("ldmatrix.sync.aligned.m8n8.x4.shared.b16 {%0,%1,%2,%3}, [%4];"
        : "=r"(r0), "=r"(r1), "=r"(r2), "=r"(r3) : "r"(addr));
}
__device__ __forceinline__ void mma16816(float* c, const uint32_t* a, uint32_t b0, uint32_t b1) {
    asm volatile("mma.sync.aligned.m16n8k16.row.col.f32.f16.f16.f32 "
        "{%0,%1,%2,%3}, {%4,%5,%6,%7}, {%8,%9}, {%0,%1,%2,%3};"
        : "+f"(c[0]), "+f"(c[1]), "+f"(c[2]), "+f"(c[3])
        : "r"(a[0]), "r"(a[1]), "r"(a[2]), "r"(a[3]), "r"(b0), "r"(b1));
}

// ---------------- scratch (fp32 everywhere) ----------------
__device__ float g_pe  [(size_t)P2_ * D_];
__device__ float g_wqt [(size_t)D_ * D_];
__device__ float g_wkt [(size_t)D_ * D_];
__device__ float g_wvt [(size_t)D_ * D_];
__device__ float g_wot [(size_t)D_ * D_];
__device__ float g_wpt [(size_t)D_ * D_];
__device__ float g_keyt[(size_t)NC_ * D_];
__device__ float g_valt[(size_t)D_ * NC_];
__device__ float g_x2  [(size_t)T_ * D_];
__device__ float g_qb  [(size_t)T_ * D_];
__device__ float g_kb  [(size_t)T_ * D_];
__device__ float g_vb  [(size_t)T_ * D_];
__device__ float g_pb  [(size_t)P2_ * D_];
__device__ float g_sc  [(size_t)B_*H_*L_*L_];
__device__ float g_ctx [(size_t)T_ * D_];
__device__ float g_xr  [(size_t)T_ * D_];
__device__ float g_tb  [(size_t)T_ * D_];
__device__ float g_gate[(size_t)T_ * E_];
__device__ float g_hb  [(size_t)T_ * NC_];

// ---------------- positional encoding ----------------
__global__ __launch_bounds__(256) void k_pos(float* __restrict__ pe) {
    int r = blockIdx.x;
    double pos = (double)(L_ - 1 - r);
    const double c = -9.210340371976184 / (double)D_;
    for (int m = threadIdx.x; m < D_; m += 256) {
        int j = (m < 512) ? m : m - 512;
        double ang = pos * exp(c * (2.0 * (double)j));
        pe[(size_t)r * D_ + m] = (float)((m < 512) ? sin(ang) : cos(ang));
    }
}

// ---------------- transpose fp32 [R,C] -> fp32 [C,R], z-batched ----------------
__global__ __launch_bounds__(256) void k_tr(const float* __restrict__ in, float* __restrict__ out,
                                            int R, int C) {
    __shared__ float t[32][33];
    size_t zoff = (size_t)blockIdx.z * R * C;
    int c0 = blockIdx.x * 32, r0 = blockIdx.y * 32;
    int x = threadIdx.x & 31, y = threadIdx.x >> 5;
    for (int i = y; i < 32; i += 8)
        t[i][x] = in[zoff + (size_t)(r0 + i) * C + c0 + x];
    __syncthreads();
    for (int i = y; i < 32; i += 8)
        out[zoff + (size_t)(c0 + i) * R + r0 + x] = t[x][i];
}

// ---------------- layer norm fp32 -> fp32 ----------------
__global__ __launch_bounds__(256) void k_ln(const float* __restrict__ x,
                                            const float* __restrict__ g,
                                            const float* __restrict__ b,
                                            float* __restrict__ o) {
    __shared__ float rs[256], rq[256];
    size_t row = blockIdx.x;
    int tid = threadIdx.x;
    float4 v = reinterpret_cast<const float4*>(x + row * D_)[tid];
    rs[tid] = v.x + v.y + v.z + v.w;
    rq[tid] = v.x*v.x + v.y*v.y + v.z*v.z + v.w*v.w;
    __syncthreads();
    for (int s = 128; s; s >>= 1) {
        if (tid < s) { rs[tid] += rs[tid+s]; rq[tid] += rq[tid+s]; }
        __syncthreads();
    }
    float mean = rs[0] * (1.0f / D_);
    float inv  = rsqrtf(rq[0] * (1.0f / D_) - mean * mean + 1e-5f);
    float4 gv = reinterpret_cast<const float4*>(g)[tid];
    float4 bv = reinterpret_cast<const float4*>(b)[tid];
    float4 ov;
    ov.x = (v.x - mean) * inv * gv.x + bv.x;
    ov.y = (v.y - mean) * inv * gv.y + bv.y;
    ov.z = (v.z - mean) * inv * gv.z + bv.z;
    ov.w = (v.w - mean) * inv * gv.w + bv.w;
    reinterpret_cast<float4*>(o + row * D_)[tid] = ov;
}

// ---------------- split-fp16 3-pass HMMA GEMM: C[M,N] = A[M,K] @ Bt[N,K]^T ----------------
// fp32 in/out. A,B split into hi+lo fp16 in smem; C = Ah*Bh + Ah*Bl + Al*Bh (fp32 accum).
// EPI 0: plain   1: + aux residual   2: relu(.)*gate
// QKV=1: blockIdx.z selects (B0,C0)/(B1,C1)/(B2,C2)
template<int EPI, int QKV>
__global__ __launch_bounds__(256) void k_hgemm3(const float* __restrict__ A,
                                                const float* __restrict__ B0,
                                                const float* __restrict__ B1,
                                                const float* __restrict__ B2,
                                                float* __restrict__ C0,
                                                float* __restrict__ C1,
                                                float* __restrict__ C2,
                                                const float* __restrict__ aux,
                                                const float* __restrict__ gate,
                                                int M, int K) {
    __shared__ half_t Ah[128 * 40], Al[128 * 40];
    __shared__ half_t Bh[128 * 40], Bl[128 * 40];
    const float* Bt = B0;
    float* Cf = C0;
    if (QKV) {
        if (blockIdx.z == 1) { Bt = B1; Cf = C1; }
        else if (blockIdx.z == 2) { Bt = B2; Cf = C2; }
    }
    const int tid = threadIdx.x, wid = tid >> 5, lane = tid & 31;
    const int m0 = blockIdx.y * 128, n0 = blockIdx.x * 128;
    const int ldc = gridDim.x * 128;
    const int wm0 = (wid & 3) * 32;
    const int wn0 = (wid >> 2) * 64;
    const uint32_t sAh = smem_u32(Ah), sAl = smem_u32(Al);
    const uint32_t sBh = smem_u32(Bh), sBl = smem_u32(Bl);

    float acc[2][8][4];
#pragma unroll
    for (int i = 0; i < 2; i++)
#pragma unroll
        for (int j = 0; j < 8; j++)
#pragma unroll
            for (int q = 0; q < 4; q++) acc[i][j][q] = 0.f;

    for (int k0 = 0; k0 < K; k0 += 32) {
        __syncthreads();
#pragma unroll
        for (int r = 0; r < 4; r++) {
            int id = tid + r * 256;          // 0..1023
            int row = id >> 3, q = id & 7;   // row 0..127, float4 chunk 0..7
            int off = row * 40 + q * 4;
            // A
            int m = m0 + row;
            float4 va = make_float4(0.f, 0.f, 0.f, 0.f);
            if (m < M) va = *reinterpret_cast<const float4*>(A + (size_t)m * K + k0 + q * 4);
            half_t h0 = __float2half_rn(va.x), h1 = __float2half_rn(va.y);
            half_t h2 = __float2half_rn(va.z), h3 = __float2half_rn(va.w);
            reinterpret_cast<__half2*>(&Ah[off])[0] = __halves2half2(h0, h1);
            reinterpret_cast<__half2*>(&Ah[off])[1] = __halves2half2(h2, h3);
            reinterpret_cast<__half2*>(&Al[off])[0] = __halves2half2(
                __float2half_rn(va.x - __half2float(h0)), __float2half_rn(va.y - __half2float(h1)));
            reinterpret_cast<__half2*>(&Al[off])[1] = __halves2half2(
                __float2half_rn(va.z - __half2float(h2)), __float2half_rn(va.w - __half2float(h3)));
            // B
            float4 vb = *reinterpret_cast<const float4*>(Bt + (size_t)(n0 + row) * K + k0 + q * 4);
            half_t g0 = __float2half_rn(vb.x), g1 = __float2half_rn(vb.y);
            half_t g2 = __float2half_rn(vb.z), g3 = __float2half_rn(vb.w);
            reinterpret_cast<__half2*>(&Bh[off])[0] = __halves2half2(g0, g1);
            reinterpret_cast<__half2*>(&Bh[off])[1] = __halves2half2(g2, g3);
            reinterpret_cast<__half2*>(&Bl[off])[0] = __halves2half2(
                __float2half_rn(vb.x - __half2float(g0)), __float2half_rn(vb.y - __half2float(g1)));
            reinterpret_cast<__half2*>(&Bl[off])[1] = __halves2half2(
                __float2half_rn(vb.z - __half2float(g2)), __float2half_rn(vb.w - __half2float(g3)));
        }
        __syncthreads();
#pragma unroll
        for (int ks = 0; ks < 2; ks++) {
            uint32_t bh[16], bl[16];
            int g = lane >> 3;
#pragma unroll
            for (int p = 0; p < 4; p++) {
                uint32_t boff = (uint32_t)(((wn0 + p * 16 + (g >> 1) * 8 + (lane & 7)) * 40
                                            + ks * 16 + (g & 1) * 8) * 2);
                ldsm4(bh[p*4+0], bh[p*4+1], bh[p*4+2], bh[p*4+3], sBh + boff);
                ldsm4(bl[p*4+0], bl[p*4+1], bl[p*4+2], bl[p*4+3], sBl + boff);
            }
#pragma unroll
            for (int am = 0; am < 2; am++) {
                uint32_t ah[4], al[4];
                uint32_t aoff = (uint32_t)(((wm0 + am * 16 + (lane & 15)) * 40
                                            + ks * 16 + (lane >> 4) * 8) * 2);
                ldsm4(ah[0], ah[1], ah[2], ah[3], sAh + aoff);
                ldsm4(al[0], al[1], al[2], al[3], sAl + aoff);
#pragma unroll
                for (int bn = 0; bn < 8; bn++) {
                    mma16816(acc[am][bn], ah, bh[bn*2], bh[bn*2+1]);
                    mma16816(acc[am][bn], ah, bl[bn*2], bl[bn*2+1]);
                    mma16816(acc[am][bn], al, bh[bn*2], bh[bn*2+1]);
                }
            }
        }
    }

    // epilogue
#pragma unroll
    for (int am = 0; am < 2; am++) {
        int r0 = m0 + wm0 + am * 16 + (lane >> 2);
        int r1 = r0 + 8;
#pragma unroll
        for (int bn = 0; bn < 8; bn++) {
            int cN = n0 + wn0 + bn * 8 + (lane & 3) * 2;
            float* a4 = acc[am][bn];
            if (EPI == 0) {
                if (r0 < M) *reinterpret_cast<float2*>(Cf + (size_t)r0 * ldc + cN) = make_float2(a4[0], a4[1]);
                if (r1 < M) *reinterpret_cast<float2*>(Cf + (size_t)r1 * ldc + cN) = make_float2(a4[2], a4[3]);
            } else if (EPI == 1) {
                if (r0 < M) {
                    float2 x = *reinterpret_cast<const float2*>(aux + (size_t)r0 * ldc + cN);
                    *reinterpret_cast<float2*>(Cf + (size_t)r0 * ldc + cN) = make_float2(a4[0] + x.x, a4[1] + x.y);
                }
                if (r1 < M) {
                    float2 x = *reinterpret_cast<const float2*>(aux + (size_t)r1 * ldc + cN);
                    *reinterpret_cast<float2*>(Cf + (size_t)r1 * ldc + cN) = make_float2(a4[2] + x.x, a4[3] + x.y);
                }
            } else {
                int e = cN >> 7;
                if (r0 < M) {
                    float gv = gate[r0 * E_ + e];
                    *reinterpret_cast<float2*>(Cf + (size_t)r0 * ldc + cN) =
                        make_float2(fmaxf(a4[0], 0.f) * gv, fmaxf(a4[1], 0.f) * gv);
                }
                if (r1 < M) {
                    float gv = gate[r1 * E_ + e];
                    *reinterpret_cast<float2*>(Cf + (size_t)r1 * ldc + cN) =
                        make_float2(fmaxf(a4[2], 0.f) * gv, fmaxf(a4[3], 0.f) * gv);
                }
            }
        }
    }
}

// ---------------- attention scores (fp32, fused rel-pos band) ----------------
__global__ __launch_bounds__(256) void k_scores(const float* __restrict__ q,
                                                const float* __restrict__ k,
                                                const float* __restrict__ p,
                                                float* __restrict__ sc) {
    __shared__ float Qs[32][65], Ks[32][65], Ps[63][65];
    const int bh = blockIdx.z;
    const int b = bh / H_, h = bh % H_;
    const int i0 = blockIdx.y * 32, j0 = blockIdx.x * 32;
    const int tid = threadIdx.x;
    {
        int d = tid & 63, rb = tid >> 6;
#pragma unroll
        for (int r = 0; r < 32; r += 4)
            Qs[rb + r][d] = q[(size_t)(b*L_ + i0 + rb + r) * D_ + h*DH_ + d];
#pragma unroll
        for (int r = 0; r < 32; r += 4)
            Ks[rb + r][d] = k[(size_t)(b*L_ + j0 + rb + r) * D_ + h*DH_ + d];
        int base = j0 - i0 + L_ - 32;
#pragma unroll
        for (int r = 0; r < 64; r += 4) {
            int rr = rb + r;
            if (rr < 63)
                Ps[rr][d] = p[(size_t)(base + rr) * D_ + h*DH_ + d];
        }
    }
    __syncthreads();
    const int tx = tid & 31, ty = tid >> 5;
    float s[4] = {0.f, 0.f, 0.f, 0.f};
    for (int d = 0; d < 64; d++) {
        float kv = Ks[tx][d];
#pragma unroll
        for (int ii = 0; ii < 4; ii++) {
            int il = ty * 4 + ii;
            s[ii] += Qs[il][d] * (kv + Ps[tx - il + 31][d]);
        }
    }
#pragma unroll
    for (int ii = 0; ii < 4; ii++) {
        int i = i0 + ty * 4 + ii;
        sc[((size_t)bh * L_ + i) * L_ + j0 + tx] = s[ii] * 0.125f;
    }
}

// ---------------- row softmax (in place) ----------------
__global__ __launch_bounds__(256) void k_softmax(float* __restrict__ sc) {
    __shared__ float red[256];
    size_t row = blockIdx.x;
    float* r = sc + row * L_;
    int tid = threadIdx.x;
    float4 v = reinterpret_cast<float4*>(r)[tid];
    red[tid] = fmaxf(fmaxf(v.x, v.y), fmaxf(v.z, v.w));
    __syncthreads();
    for (int s = 128; s; s >>= 1) {
        if (tid < s) red[tid] = fmaxf(red[tid], red[tid+s]);
        __syncthreads();
    }
    float mx = red[0];
    __syncthreads();
    v.x = expf(v.x - mx); v.y = expf(v.y - mx);
    v.z = expf(v.z - mx); v.w = expf(v.w - mx);
    red[tid] = v.x + v.y + v.z + v.w;
    __syncthreads();
    for (int s = 128; s; s >>= 1) {
        if (tid < s) red[tid] += red[tid+s];
        __syncthreads();
    }
    float inv = 1.f / red[0];
    v.x *= inv; v.y *= inv; v.z *= inv; v.w *= inv;
    reinterpret_cast<float4*>(r)[tid] = v;
}

// ---------------- ctx = att @ v -> fp32 [b,i,h*64+d] ----------------
__global__ __launch_bounds__(256) void k_av(const float* __restrict__ sc,
                                            const float* __restrict__ v,
                                            float* __restrict__ ctx) {
    __shared__ float As[64][33];
    __shared__ float Vs[32][64];
    const int bh = blockIdx.y, b = bh / H_, h = bh % H_;
    const int i0 = blockIdx.x * 64;
    const int tid = threadIdx.x;
    const int tx = tid & 15, ty = tid >> 4;
    float acc[4][4] = {};
    for (int j0 = 0; j0 < L_; j0 += 32) {
        {
            int kk = tid & 31, ib = tid >> 5;
#pragma unroll
            for (int r = 0; r < 64; r += 8)
                As[ib + r][kk] = sc[((size_t)bh * L_ + i0 + ib + r) * L_ + j0 + kk];
            int d = tid & 63, kb2 = tid >> 6;
#pragma unroll
            for (int r = 0; r < 32; r += 4)
                Vs[kb2 + r][d] = v[(size_t)(b*L_ + j0 + kb2 + r) * D_ + h*DH_ + d];
        }
        __syncthreads();
#pragma unroll
        for (int kk = 0; kk < 32; kk++) {
            float a0 = As[ty*4+0][kk], a1 = As[ty*4+1][kk];
            float a2 = As[ty*4+2][kk], a3 = As[ty*4+3][kk];
            float4 bq = *reinterpret_cast<const float4*>(&Vs[kk][tx*4]);
            acc[0][0] += a0*bq.x; acc[0][1] += a0*bq.y; acc[0][2] += a0*bq.z; acc[0][3] += a0*bq.w;
            acc[1][0] += a1*bq.x; acc[1][1] += a1*bq.y; acc[1][2] += a1*bq.z; acc[1][3] += a1*bq.w;
            acc[2][0] += a2*bq.x; acc[2][1] += a2*bq.y; acc[2][2] += a2*bq.z; acc[2][3] += a2*bq.w;
            acc[3][0] += a3*bq.x; acc[3][1] += a3*bq.y; acc[3][2] += a3*bq.z; acc[3][3] += a3*bq.w;
        }
        __syncthreads();
    }
#pragma unroll
    for (int i = 0; i < 4; i++)
#pragma unroll
        for (int j = 0; j < 4; j++)
            ctx[(size_t)(b*L_ + i0 + ty*4 + i) * D_ + h*DH_ + tx*4 + j] = acc[i][j];
}

// ---------------- gating ----------------
__global__ __launch_bounds__(256) void k_gates(const float* __restrict__ t,
                                               const float* __restrict__ sw,
                                               float* __restrict__ gate) {
    __shared__ float ts[D_];
    const int tok = blockIdx.x;
    const int tid = threadIdx.x;
    reinterpret_cast<float4*>(ts)[tid] =
        reinterpret_cast<const float4*>(t + (size_t)tok * D_)[tid];
    __syncthreads();
    if (tid < 32) {
        float acc = 0.f;
        for (int d = 0; d < D_; d++) acc += ts[d] * sw[d * E_ + tid];
        float gv = 1.f / (1.f + expf(-acc));
        bool sel = false;
        for (int r = 0; r < 4; r++) {
            float cand = sel ? -1e30f : gv;
            float bv = cand; int bi = tid;
            for (int off = 16; off; off >>= 1) {
                float ov = __shfl_xor_sync(0xffffffffu, bv, off);
                int oi = __shfl_xor_sync(0xffffffffu, bi, off);
                if (ov > bv || (ov == bv && oi < bi)) { bv = ov; bi = oi; }
            }
            if (tid == bi) sel = true;
        }
        gate[tok * E_ + tid] = sel ? gv : 0.f;
    }
}

// ---------------- launch ----------------
extern "C" void kernel_launch(void* const* d_in, const int* in_sizes, int n_in,
                              void* d_out, int out_size) {
    const float* src  = (const float*)d_in[0];
    const float* Wq   = (const float*)d_in[1];
    const float* Wk   = (const float*)d_in[2];
    const float* Wv   = (const float*)d_in[3];
    const float* Wo   = (const float*)d_in[4];
    const float* Wp   = (const float*)d_in[5];
    const float* ln1g = (const float*)d_in[6];
    const float* ln1b = (const float*)d_in[7];
    const float* ln2g = (const float*)d_in[8];
    const float* ln2b = (const float*)d_in[9];
    const float* selw = (const float*)d_in[10];
    const float* keys = (const float*)d_in[11];
    const float* vals = (const float*)d_in[12];
    float* out = (float*)d_out;

    float *pe, *wqt, *wkt, *wvt, *wot, *wpt, *keyt, *valt;
    float *x2, *qb, *kb, *vb, *pb, *sc, *ctx, *xr, *tb, *gate, *hb;
    cudaGetSymbolAddress((void**)&pe,   g_pe);
    cudaGetSymbolAddress((void**)&wqt,  g_wqt);
    cudaGetSymbolAddress((void**)&wkt,  g_wkt);
    cudaGetSymbolAddress((void**)&wvt,  g_wvt);
    cudaGetSymbolAddress((void**)&wot,  g_wot);
    cudaGetSymbolAddress((void**)&wpt,  g_wpt);
    cudaGetSymbolAddress((void**)&keyt, g_keyt);
    cudaGetSymbolAddress((void**)&valt, g_valt);
    cudaGetSymbolAddress((void**)&x2,   g_x2);
    cudaGetSymbolAddress((void**)&qb,   g_qb);
    cudaGetSymbolAddress((void**)&kb,   g_kb);
    cudaGetSymbolAddress((void**)&vb,   g_vb);
    cudaGetSymbolAddress((void**)&pb,   g_pb);
    cudaGetSymbolAddress((void**)&sc,   g_sc);
    cudaGetSymbolAddress((void**)&ctx,  g_ctx);
    cudaGetSymbolAddress((void**)&xr,   g_xr);
    cudaGetSymbolAddress((void**)&tb,   g_tb);
    cudaGetSymbolAddress((void**)&gate, g_gate);
    cudaGetSymbolAddress((void**)&hb,   g_hb);

    // prep
    k_pos<<<P2_, 256>>>(pe);
    dim3 g1k(32, 32, 1);
    k_tr<<<g1k, 256>>>(Wq, wqt, D_, D_);
    k_tr<<<g1k, 256>>>(Wk, wkt, D_, D_);
    k_tr<<<g1k, 256>>>(Wv, wvt, D_, D_);
    k_tr<<<g1k, 256>>>(Wo, wot, D_, D_);
    k_tr<<<g1k, 256>>>(Wp, wpt, D_, D_);
    k_tr<<<dim3(4, 32, E_), 256>>>(keys, keyt, D_, ES_);
    k_tr<<<dim3(32, 128, 1), 256>>>(vals, valt, NC_, D_);

    k_ln<<<T_, 256>>>(src, ln1g, ln1b, x2);

    // Q,K,V fused (z) + P projection — split-fp16 3-pass HMMA
    k_hgemm3<0, 1><<<dim3(8, 16, 3), 256>>>(x2, wqt, wkt, wvt, qb, kb, vb, nullptr, nullptr, T_, D_);
    k_hgemm3<0, 0><<<dim3(8, 16), 256>>>(pe, wpt, nullptr, nullptr, pb, nullptr, nullptr, nullptr, nullptr, P2_, D_);

    k_scores<<<dim3(L_/32, L_/32, B_*H_), 256>>>(qb, kb, pb, sc);
    k_softmax<<<B_*H_*L_, 256>>>(sc);
    k_av<<<dim3(L_/64, B_*H_), 256>>>(sc, vb, ctx);
    k_hgemm3<1, 0><<<dim3(8, 16), 256>>>(ctx, wot, nullptr, nullptr, xr, nullptr, nullptr, src, nullptr, T_, D_);

    k_ln<<<T_, 256>>>(xr, ln2g, ln2b, tb);
    k_gates<<<T_, 256>>>(tb, selw, gate);
    k_hgemm3<2, 0><<<dim3(32, 16), 256>>>(tb, keyt, nullptr, nullptr, hb, nullptr, nullptr, nullptr, gate, T_, D_);
    k_hgemm3<1, 0><<<dim3(8, 16), 256>>>(hb, valt, nullptr, nullptr, out, nullptr, nullptr, xr, nullptr, T_, NC_);
}